// round 13
// baseline (speedup 1.0000x reference)
#include <cuda_runtime.h>
#include <cuda_bf16.h>
#include <cstdint>
#include <math.h>

// PaiNN interaction — fused HMMA bf16 kernel, round 13.
// R12 neutral: barrier scope wasn't the residual. L1 59% vs tensor 29% -> lengthen
// compute runs: K-chunks of 128 (7 chunks vs 13), 2-stage ring with
// wait -> bar -> stage -> compute schedule so staging drains under compute.
//
// Inputs: 0 s [N,128] f32, 1 v [N,3,128] f32, 2 pos [N,3] f32, 3 edge_index [2,E],
// 4 W1 [276,256], 5 b1, 6 W2, 7 b2, 8 Ws, 9 bs, 10 Wv, 11 bv, 12 centers, 13 widths
// Output: concat(s_out [N,128], v_out [N,3,128]) f32.

#define FDIM 128
#define NRBF 20
#define IN_DIM 276
#define K1 320
#define K23 256
#define TILE_E 128
#define NTHREADS 1024
#define NCHUNK_TOT 7         // L0: 128,128,64 ; L1: 128,128 ; L2: 128,128

#define APAIRS 164           // u32 per A row (328 bf16); 164 % 32 == 4 (bank-perfect)
#define A_BYTES (TILE_E * APAIRS * 4)            // 83968
#define BROW_BYTES 272       // row stride (68 u32; 68 % 32 == 4); 256B data max
#define B_BYTES (256 * BROW_BYTES)               // 69632
#define DST_OFF (A_BYTES + 2 * B_BYTES)
#define DIR_OFF (DST_OFF + 512)
#define SMEM_TOTAL (DIR_OFF + 1536)              // 225280 -> 1 CTA/SM

// ---------------- device globals ----------------
__device__ __align__(16) __nv_bfloat16 g_W1T[256 * K1];    // [n][k], k>=276 zero
__device__ __align__(16) __nv_bfloat16 g_W2T[256 * K23];
__device__ __align__(16) __nv_bfloat16 g_WsvT[256 * K23];  // n<128 Ws, n>=128 Wv
__device__ int g_idx64;

// ---------------- helpers ----------------
__device__ __forceinline__ uint32_t smem_u32(const void* p) {
    uint32_t a;
    asm("{ .reg .u64 t; cvta.to.shared.u64 t, %1; cvt.u32.u64 %0, t; }" : "=r"(a) : "l"(p));
    return a;
}
__device__ __forceinline__ uint32_t packbf(float a, float b) {
    __nv_bfloat162 h = __floats2bfloat162_rn(a, b);
    return *reinterpret_cast<uint32_t*>(&h);
}
__device__ __forceinline__ float silu(float x) { return x / (1.0f + __expf(-x)); }

__device__ __forceinline__ void mma16816(float c[4], uint32_t a0, uint32_t a1, uint32_t a2,
                                         uint32_t a3, uint32_t b0, uint32_t b1) {
    asm volatile(
        "mma.sync.aligned.m16n8k16.row.col.f32.bf16.bf16.f32 "
        "{%0,%1,%2,%3}, {%4,%5,%6,%7}, {%8,%9}, {%0,%1,%2,%3};"
        : "+f"(c[0]), "+f"(c[1]), "+f"(c[2]), "+f"(c[3])
        : "r"(a0), "r"(a1), "r"(a2), "r"(a3), "r"(b0), "r"(b1));
}

__device__ __forceinline__ void ldm_x4(uint32_t r[4], uint32_t addr) {
    asm volatile("ldmatrix.sync.aligned.m8n8.x4.shared.b16 {%0,%1,%2,%3}, [%4];"
                 : "=r"(r[0]), "=r"(r[1]), "=r"(r[2]), "=r"(r[3]) : "r"(addr));
}

__device__ __forceinline__ void cpasync16(uint32_t dst, const void* src) {
    asm volatile("cp.async.cg.shared.global [%0], [%1], 16;" :: "r"(dst), "l"(src)
                 : "memory");
}

__device__ __forceinline__ void red2(float* p, float a, float b) {
    asm volatile("red.global.add.v2.f32 [%0], {%1, %2};" :: "l"(p), "f"(a), "f"(b) : "memory");
}

#define HALF_BAR(h) asm volatile("bar.sync %0, %1;" :: "r"((h) + 1), "r"(512) : "memory")

__device__ __forceinline__ long long load_idx(const void* p, long long i, int is64) {
    if (is64) return ((const long long*)p)[i];
    return (long long)((const int*)p)[i];
}

// chunk index -> weight matrix / k-offset / K stride / chunk k-width
__device__ __forceinline__ void chunk_src(int gc, const __nv_bfloat16*& w, int& c0,
                                          int& Kl, int& kw) {
    if (gc < 3)      { w = g_W1T;  c0 = gc * 128;       Kl = K1;  kw = (gc == 2) ? 64 : 128; }
    else if (gc < 5) { w = g_W2T;  c0 = (gc - 3) * 128; Kl = K23; kw = 128; }
    else             { w = g_WsvT; c0 = (gc - 5) * 128; Kl = K23; kw = 128; }
}

// stage this half's 128 rows of one chunk (kw bytes/row) into a ring slot
__device__ __forceinline__ void stage_half(uint32_t slotbase, const __nv_bfloat16* w,
                                           int c0, int Kl, int kw, int h, int tih) {
    if (kw == 128) {   // 256B/row, 16 units/row, 2048 units/half
#pragma unroll
        for (int u = 0; u < 4; ++u) {
            int unit = tih + u * 512;
            int row = h * 128 + (unit >> 4);
            int sub = unit & 15;
            cpasync16(slotbase + row * BROW_BYTES + sub * 16,
                      (const char*)(w + (size_t)row * Kl + c0) + sub * 16);
        }
    } else {           // 128B/row, 8 units/row, 1024 units/half
#pragma unroll
        for (int u = 0; u < 2; ++u) {
            int unit = tih + u * 512;
            int row = h * 128 + (unit >> 3);
            int sub = unit & 7;
            cpasync16(slotbase + row * BROW_BYTES + sub * 16,
                      (const char*)(w + (size_t)row * Kl + c0) + sub * 16);
        }
    }
    asm volatile("cp.async.commit_group;" ::: "memory");
}

// ---------------- small helper kernels ----------------
__global__ void detect_idx_kernel(const int* __restrict__ idx32) {
    __shared__ int nz;
    if (threadIdx.x == 0) nz = 0;
    __syncthreads();
    int v = idx32[2 * threadIdx.x + 1];
    if (v != 0) atomicOr(&nz, 1);
    __syncthreads();
    if (threadIdx.x == 0) g_idx64 = (nz == 0) ? 1 : 0;
}

__global__ void init_out_kernel(const float4* __restrict__ s, const float4* __restrict__ v,
                                float4* __restrict__ out, int ns4, int nv4) {
    int stride = gridDim.x * blockDim.x;
    for (int i = blockIdx.x * blockDim.x + threadIdx.x; i < ns4; i += stride) out[i] = s[i];
    for (int i = blockIdx.x * blockDim.x + threadIdx.x; i < nv4; i += stride)
        out[ns4 + i] = v[i];
}

__global__ void prep_weights(const float* __restrict__ W1, const float* __restrict__ W2,
                             const float* __restrict__ Ws, const float* __restrict__ Wv) {
    const int t1 = 256 * K1;
    const int t2 = t1 + 256 * K23;
    const int t3 = t2 + 256 * K23;
    int stride = gridDim.x * blockDim.x;
    for (int idx = blockIdx.x * blockDim.x + threadIdx.x; idx < t3; idx += stride) {
        if (idx < t1) {
            int n = idx / K1, k = idx % K1;
            g_W1T[idx] = __float2bfloat16((k < IN_DIM) ? W1[k * 256 + n] : 0.0f);
        } else if (idx < t2) {
            int r = idx - t1;
            int n = r / K23, k = r % K23;
            g_W2T[r] = __float2bfloat16(W2[k * 256 + n]);
        } else {
            int r = idx - t2;
            int n = r / K23, k = r % K23;
            float val = (n < FDIM) ? Ws[k * FDIM + n] : Wv[k * FDIM + (n - FDIM)];
            g_WsvT[r] = __float2bfloat16(val);
        }
    }
}

// ---------------- main fused kernel ----------------
__global__ __launch_bounds__(NTHREADS, 1)
void painn_mma_kernel(const float* __restrict__ s, const float* __restrict__ pos,
                      const void* __restrict__ eidx,
                      const float* __restrict__ b1, const float* __restrict__ b2,
                      const float* __restrict__ bs, const float* __restrict__ bv,
                      const float* __restrict__ centers, const float* __restrict__ widths,
                      float* __restrict__ out_s, float* __restrict__ out_v, int E) {
    extern __shared__ char smem[];
    uint32_t* A32 = (uint32_t*)smem;                    // [128][164] bf16 pairs
    int* dstS = (int*)(smem + DST_OFF);
    float* dirS = (float*)(smem + DIR_OFF);
    const uint32_t Abase = smem_u32(smem);

    const int tid = threadIdx.x;
    const int wid = tid >> 5;
    const int lane = tid & 31;
    const int g = lane >> 2;
    const int tig = lane & 3;
    const int quad = lane >> 3;
    const int rowin = lane & 7;
    const int warp_m = wid & 3;     // 4 M-warps x 32 rows
    const int warp_n = wid >> 2;    // 8 N-warps x 32 cols
    const int m0 = warp_m * 32;
    const int n0 = warp_n * 32;
    const int h = tid >> 9;         // CTA half (0: n<128, 1: n>=128)
    const int tih = tid & 511;

    const int is64 = g_idx64;
    const long long e0 = (long long)blockIdx.x * TILE_E;

    // hoisted ldmatrix addressing
    uint32_t a_addr0 = Abase +
        ((uint32_t)((m0 + (quad & 1) * 8 + rowin) * APAIRS + (quad >> 1) * 4)) * 4u;
    uint32_t a_addr1 = a_addr0 + 16u * APAIRS * 4u;
    uint32_t b_off0 = (uint32_t)(n0 + (quad >> 1) * 8 + rowin) * BROW_BYTES +
                      (uint32_t)(quad & 1) * 16u;
    uint32_t b_off1 = b_off0 + 16u * BROW_BYTES;

    // ---- prologue: stage own half of chunk 0 into ring slot 0 ----
    {
        const __nv_bfloat16* w; int c0, Kl, kw;
        chunk_src(0, w, c0, Kl, kw);
        stage_half(Abase + A_BYTES, w, c0, Kl, kw, h, tih);
    }

    // ---- build A + meta: 8 threads per edge ----
    {
        const int m = tid >> 3;
        const int c = tid & 7;
        const bool valid = (e0 + m) < (long long)E;
        if (valid) {
            long long srcI = load_idx(eidx, e0 + m, is64);
            long long dstI = load_idx(eidx, (long long)E + e0 + m, is64);
            long long node = (c < 4) ? srcI : dstI;
            const int qq = c & 3;
            const float4* rp = (const float4*)(s + node * FDIM) + qq * 8;
            uint32_t* Arow = A32 + m * APAIRS + c * 16;
#pragma unroll
            for (int q = 0; q < 8; ++q) {
                float4 t = __ldg(rp + q);
                Arow[2 * q]     = packbf(t.x, t.y);
                Arow[2 * q + 1] = packbf(t.z, t.w);
            }
            if (c == 0) {
                float rx = pos[dstI * 3 + 0] - pos[srcI * 3 + 0];
                float ry = pos[dstI * 3 + 1] - pos[srcI * 3 + 1];
                float rz = pos[dstI * 3 + 2] - pos[srcI * 3 + 2];
                float d2 = rx * rx + ry * ry + rz * rz;
                float dist = sqrtf(d2);
                float inv = (d2 > 0.f) ? (1.0f / dist) : 0.0f;
                dstS[m] = (int)dstI;
                dirS[m * 3 + 0] = rx * inv;
                dirS[m * 3 + 1] = ry * inv;
                dirS[m * 3 + 2] = rz * inv;
            } else if (c == 7) {
                float rx = pos[dstI * 3 + 0] - pos[srcI * 3 + 0];
                float ry = pos[dstI * 3 + 1] - pos[srcI * 3 + 1];
                float rz = pos[dstI * 3 + 2] - pos[srcI * 3 + 2];
                float dist = sqrtf(rx * rx + ry * ry + rz * rz);
                uint32_t* Ar = A32 + m * APAIRS + 128;
#pragma unroll
                for (int j = 0; j < 32; ++j) {
                    float f0 = 0.f, f1 = 0.f;
                    int j0 = 2 * j, j1 = 2 * j + 1;
                    if (j0 < NRBF) {
                        float t = (dist - __ldg(centers + j0)) / (__ldg(widths + j0) + 1e-8f);
                        f0 = __expf(-t * t);
                    }
                    if (j1 < NRBF) {
                        float t = (dist - __ldg(centers + j1)) / (__ldg(widths + j1) + 1e-8f);
                        f1 = __expf(-t * t);
                    }
                    Ar[j] = packbf(f0, f1);
                }
                A32[m * APAIRS + 160] = 0; A32[m * APAIRS + 161] = 0;
                A32[m * APAIRS + 162] = 0; A32[m * APAIRS + 163] = 0;
            }
        } else {
            uint32_t* Arow = A32 + m * APAIRS + c * 16;
#pragma unroll
            for (int q = 0; q < 16; ++q) Arow[q] = 0;
            if (c == 0) dstS[m] = -1;
            if (c == 7) {
                uint32_t* Ar = A32 + m * APAIRS + 128;
#pragma unroll
                for (int j = 0; j < 36; ++j) Ar[j] = 0;
            }
        }
    }
    __syncthreads();   // A visible to both halves

    float acc[2][4][4];
    int gc = 0;

#pragma unroll 1
    for (int L = 0; L < 3; ++L) {
        const int nch = (L == 0) ? 3 : 2;

#pragma unroll
        for (int mb = 0; mb < 2; ++mb)
#pragma unroll
            for (int t = 0; t < 4; ++t)
#pragma unroll
                for (int i = 0; i < 4; ++i) acc[mb][t][i] = 0.f;

#pragma unroll 1
        for (int c = 0; c < nch; ++c) {
            const int gcl = gc;
            const __nv_bfloat16* w; int c0, Kl, kw;
            chunk_src(gcl, w, c0, Kl, kw);

            asm volatile("cp.async.wait_group 0;" ::: "memory");   // chunk gcl landed
            HALF_BAR(h);   // publish chunk gcl; retire slot (gcl+1)%2's consumers

            // stage NEXT chunk into the other slot (drains under compute below)
            if (gcl + 1 < NCHUNK_TOT) {
                const __nv_bfloat16* nw; int nc0, nKl, nkw;
                chunk_src(gcl + 1, nw, nc0, nKl, nkw);
                stage_half(Abase + A_BYTES + ((gcl + 1) & 1) * B_BYTES, nw, nc0, nKl, nkw,
                           h, tih);
            }

            const uint32_t Bc = Abase + A_BYTES + (gcl & 1) * B_BYTES;
            uint32_t aa0 = a_addr0 + (uint32_t)c0 * 2u;
            uint32_t aa1 = a_addr1 + (uint32_t)c0 * 2u;
            uint32_t bb0 = Bc + b_off0;
            uint32_t bb1 = Bc + b_off1;
            const int nks = kw >> 4;
#pragma unroll 1
            for (int ks = 0; ks < nks; ++ks) {
                uint32_t afr[2][4];
                ldm_x4(afr[0], aa0);
                ldm_x4(afr[1], aa1);
                uint32_t bfr0[4], bfr1[4];
                ldm_x4(bfr0, bb0);
                ldm_x4(bfr1, bb1);
#pragma unroll
                for (int mb = 0; mb < 2; ++mb) {
                    mma16816(acc[mb][0], afr[mb][0], afr[mb][1], afr[mb][2], afr[mb][3],
                             bfr0[0], bfr0[1]);
                    mma16816(acc[mb][1], afr[mb][0], afr[mb][1], afr[mb][2], afr[mb][3],
                             bfr0[2], bfr0[3]);
                    mma16816(acc[mb][2], afr[mb][0], afr[mb][1], afr[mb][2], afr[mb][3],
                             bfr1[0], bfr1[1]);
                    mma16816(acc[mb][3], afr[mb][0], afr[mb][1], afr[mb][2], afr[mb][3],
                             bfr1[2], bfr1[3]);
                }
                aa0 += 32u; aa1 += 32u; bb0 += 32u; bb1 += 32u;
            }
            gc++;
        }
        __syncthreads();   // layer compute done (both halves) before A overwrite / scatter

        if (L < 2) {
            const float* bias = (L == 0) ? b1 : b2;
#pragma unroll
            for (int mb = 0; mb < 2; ++mb) {
                const int r0 = m0 + mb * 16 + g;
#pragma unroll
                for (int t = 0; t < 4; ++t) {
                    const int col = n0 + t * 8 + tig * 2;
                    float bb0v = __ldg(bias + col);
                    float bb1v = __ldg(bias + col + 1);
                    const int pr = col >> 1;
                    A32[r0 * APAIRS + pr] =
                        packbf(silu(acc[mb][t][0] + bb0v), silu(acc[mb][t][1] + bb1v));
                    A32[(r0 + 8) * APAIRS + pr] =
                        packbf(silu(acc[mb][t][2] + bb0v), silu(acc[mb][t][3] + bb1v));
                }
            }
            __syncthreads();   // new A visible to both halves before next layer
        } else {
            // scatter: half 0 -> ds (cols 0..127); half 1 -> dv
#pragma unroll
            for (int mb = 0; mb < 2; ++mb) {
                const int r0 = m0 + mb * 16 + g, r1 = r0 + 8;
                const int d0 = dstS[r0], d1 = dstS[r1];
                if (h == 0) {
#pragma unroll
                    for (int t = 0; t < 4; ++t) {
                        const int col = n0 + t * 8 + tig * 2;
                        float bb0v = __ldg(bs + col), bb1v = __ldg(bs + col + 1);
                        if (d0 >= 0)
                            red2(out_s + (long long)d0 * FDIM + col, acc[mb][t][0] + bb0v,
                                 acc[mb][t][1] + bb1v);
                        if (d1 >= 0)
                            red2(out_s + (long long)d1 * FDIM + col, acc[mb][t][2] + bb0v,
                                 acc[mb][t][3] + bb1v);
                    }
                } else {
                    float dx0 = dirS[r0 * 3], dy0 = dirS[r0 * 3 + 1], dz0 = dirS[r0 * 3 + 2];
                    float dx1 = dirS[r1 * 3], dy1 = dirS[r1 * 3 + 1], dz1 = dirS[r1 * 3 + 2];
#pragma unroll
                    for (int t = 0; t < 4; ++t) {
                        const int col = n0 - 128 + t * 8 + tig * 2;
                        float bb0v = __ldg(bv + col), bb1v = __ldg(bv + col + 1);
                        if (d0 >= 0) {
                            float v0 = acc[mb][t][0] + bb0v, v1 = acc[mb][t][1] + bb1v;
                            float* vb = out_v + (long long)d0 * 3 * FDIM + col;
                            red2(vb, dx0 * v0, dx0 * v1);
                            red2(vb + FDIM, dy0 * v0, dy0 * v1);
                            red2(vb + 2 * FDIM, dz0 * v0, dz0 * v1);
                        }
                        if (d1 >= 0) {
                            float v0 = acc[mb][t][2] + bb0v, v1 = acc[mb][t][3] + bb1v;
                            float* vb = out_v + (long long)d1 * 3 * FDIM + col;
                            red2(vb, dx1 * v0, dx1 * v1);
                            red2(vb + FDIM, dy1 * v0, dy1 * v1);
                            red2(vb + 2 * FDIM, dz1 * v0, dz1 * v1);
                        }
                    }
                }
            }
        }
    }
}

// ---------------- launcher ----------------
extern "C" void kernel_launch(void* const* d_in, const int* in_sizes, int n_in,
                              void* d_out, int out_size) {
    const float* s       = (const float*)d_in[0];
    const float* v       = (const float*)d_in[1];
    const float* pos     = (const float*)d_in[2];
    const void*  eidx    = d_in[3];
    const float* W1      = (const float*)d_in[4];
    const float* b1      = (const float*)d_in[5];
    const float* W2      = (const float*)d_in[6];
    const float* b2      = (const float*)d_in[7];
    const float* Ws      = (const float*)d_in[8];
    const float* bs      = (const float*)d_in[9];
    const float* Wv      = (const float*)d_in[10];
    const float* bv      = (const float*)d_in[11];
    const float* centers = (const float*)d_in[12];
    const float* widths  = (const float*)d_in[13];

    int N = in_sizes[0] / FDIM;
    int E = in_sizes[3] / 2;

    float* out_s = (float*)d_out;
    float* out_v = out_s + (long long)N * FDIM;

    detect_idx_kernel<<<1, 256>>>((const int*)eidx);

    int ns4 = N * FDIM / 4;
    int nv4 = N * 3 * FDIM / 4;
    init_out_kernel<<<1024, 256>>>((const float4*)s, (const float4*)v, (float4*)d_out, ns4, nv4);

    prep_weights<<<256, 256>>>(W1, W2, Ws, Wv);

    cudaFuncSetAttribute(painn_mma_kernel, cudaFuncAttributeMaxDynamicSharedMemorySize,
                         SMEM_TOTAL);

    int grid = (E + TILE_E - 1) / TILE_E;
    painn_mma_kernel<<<grid, NTHREADS, SMEM_TOTAL>>>(s, pos, eidx, b1, b2, bs, bv, centers,
                                                     widths, out_s, out_v, E);
}

// round 14
// speedup vs baseline: 1.1664x; 1.1664x over previous
#include <cuda_runtime.h>
#include <cuda_bf16.h>
#include <cstdint>
#include <math.h>

// PaiNN interaction — fused HMMA bf16 kernel, round 14.
// Core = round-11 kernel (best: 1237.7us). Changes ONLY in A-build:
// s pre-converted to bf16 (g_sbf) by prep kernel; A rows filled with cp.async
// (gather drains async with B prefetch). RBF cols still computed in-register.
//
// Inputs: 0 s [N,128] f32, 1 v [N,3,128] f32, 2 pos [N,3] f32, 3 edge_index [2,E],
// 4 W1 [276,256], 5 b1, 6 W2, 7 b2, 8 Ws, 9 bs, 10 Wv, 11 bv, 12 centers, 13 widths
// Output: concat(s_out [N,128], v_out [N,3,128]) f32.

#define FDIM 128
#define NRBF 20
#define IN_DIM 276
#define K1 320
#define K23 256
#define TILE_E 128
#define NTHREADS 1024
#define NCHUNK_TOT 13        // 5 + 4 + 4
#define NSTAGE 3
#define NMAX 50176           // max nodes supported for bf16 s cache

#define APAIRS 164           // u32 per A row (328 bf16); 164 % 32 == 4 (bank-perfect)
#define AROW_BYTES (APAIRS * 4)                  // 656 (16B-multiple)
#define A_BYTES (TILE_E * AROW_BYTES)            // 83968
#define BROW_BYTES 144       // smem row stride (36 u32; 36 % 32 == 4); 128B real
#define B_BYTES (256 * BROW_BYTES)               // 36864
#define DST_OFF (A_BYTES + NSTAGE * B_BYTES)
#define DIR_OFF (DST_OFF + 512)
#define SMEM_TOTAL (DIR_OFF + 1536)              // ~196KB -> 1 CTA/SM

// ---------------- device globals ----------------
__device__ __align__(16) __nv_bfloat16 g_W1T[256 * K1];    // [n][k], k>=276 zero
__device__ __align__(16) __nv_bfloat16 g_W2T[256 * K23];
__device__ __align__(16) __nv_bfloat16 g_WsvT[256 * K23];  // n<128 Ws, n>=128 Wv
__device__ __align__(16) __nv_bfloat16 g_sbf[NMAX * FDIM]; // bf16 copy of s
__device__ int g_idx64;

// ---------------- helpers ----------------
__device__ __forceinline__ uint32_t smem_u32(const void* p) {
    uint32_t a;
    asm("{ .reg .u64 t; cvta.to.shared.u64 t, %1; cvt.u32.u64 %0, t; }" : "=r"(a) : "l"(p));
    return a;
}
__device__ __forceinline__ uint32_t packbf(float a, float b) {
    __nv_bfloat162 h = __floats2bfloat162_rn(a, b);
    return *reinterpret_cast<uint32_t*>(&h);
}
__device__ __forceinline__ float silu(float x) { return x / (1.0f + __expf(-x)); }

__device__ __forceinline__ void mma16816(float c[4], uint32_t a0, uint32_t a1, uint32_t a2,
                                         uint32_t a3, uint32_t b0, uint32_t b1) {
    asm volatile(
        "mma.sync.aligned.m16n8k16.row.col.f32.bf16.bf16.f32 "
        "{%0,%1,%2,%3}, {%4,%5,%6,%7}, {%8,%9}, {%0,%1,%2,%3};"
        : "+f"(c[0]), "+f"(c[1]), "+f"(c[2]), "+f"(c[3])
        : "r"(a0), "r"(a1), "r"(a2), "r"(a3), "r"(b0), "r"(b1));
}

__device__ __forceinline__ void ldm_x4(uint32_t r[4], uint32_t addr) {
    asm volatile("ldmatrix.sync.aligned.m8n8.x4.shared.b16 {%0,%1,%2,%3}, [%4];"
                 : "=r"(r[0]), "=r"(r[1]), "=r"(r[2]), "=r"(r[3]) : "r"(addr));
}

__device__ __forceinline__ void cpasync16(uint32_t dst, const void* src) {
    asm volatile("cp.async.cg.shared.global [%0], [%1], 16;" :: "r"(dst), "l"(src)
                 : "memory");
}

__device__ __forceinline__ void red2(float* p, float a, float b) {
    asm volatile("red.global.add.v2.f32 [%0], {%1, %2};" :: "l"(p), "f"(a), "f"(b) : "memory");
}

__device__ __forceinline__ long long load_idx(const void* p, long long i, int is64) {
    if (is64) return ((const long long*)p)[i];
    return (long long)((const int*)p)[i];
}

__device__ __forceinline__ void chunk_src(int gc, const __nv_bfloat16*& w, int& c0, int& Kl) {
    if (gc < 5)      { w = g_W1T;  c0 = gc * 64;       Kl = K1; }
    else if (gc < 9) { w = g_W2T;  c0 = (gc - 5) * 64; Kl = K23; }
    else             { w = g_WsvT; c0 = (gc - 9) * 64; Kl = K23; }
}

// ---------------- small helper kernels ----------------
__global__ void detect_idx_kernel(const int* __restrict__ idx32) {
    __shared__ int nz;
    if (threadIdx.x == 0) nz = 0;
    __syncthreads();
    int v = idx32[2 * threadIdx.x + 1];
    if (v != 0) atomicOr(&nz, 1);
    __syncthreads();
    if (threadIdx.x == 0) g_idx64 = (nz == 0) ? 1 : 0;
}

__global__ void init_out_kernel(const float4* __restrict__ s, const float4* __restrict__ v,
                                float4* __restrict__ out, int ns4, int nv4) {
    int stride = gridDim.x * blockDim.x;
    for (int i = blockIdx.x * blockDim.x + threadIdx.x; i < ns4; i += stride) out[i] = s[i];
    for (int i = blockIdx.x * blockDim.x + threadIdx.x; i < nv4; i += stride)
        out[ns4 + i] = v[i];
}

__global__ void prep_weights(const float* __restrict__ W1, const float* __restrict__ W2,
                             const float* __restrict__ Ws, const float* __restrict__ Wv,
                             const float* __restrict__ s, int nselem) {
    const int t1 = 256 * K1;
    const int t2 = t1 + 256 * K23;
    const int t3 = t2 + 256 * K23;
    const int t4 = t3 + nselem;
    int stride = gridDim.x * blockDim.x;
    for (int idx = blockIdx.x * blockDim.x + threadIdx.x; idx < t4; idx += stride) {
        if (idx < t1) {
            int n = idx / K1, k = idx % K1;
            g_W1T[idx] = __float2bfloat16((k < IN_DIM) ? W1[k * 256 + n] : 0.0f);
        } else if (idx < t2) {
            int r = idx - t1;
            int n = r / K23, k = r % K23;
            g_W2T[r] = __float2bfloat16(W2[k * 256 + n]);
        } else if (idx < t3) {
            int r = idx - t2;
            int n = r / K23, k = r % K23;
            float val = (n < FDIM) ? Ws[k * FDIM + n] : Wv[k * FDIM + (n - FDIM)];
            g_WsvT[r] = __float2bfloat16(val);
        } else {
            int r = idx - t3;
            g_sbf[r] = __float2bfloat16(s[r]);
        }
    }
}

// ---------------- main fused kernel ----------------
__global__ __launch_bounds__(NTHREADS, 1)
void painn_mma_kernel(const float* __restrict__ pos,
                      const void* __restrict__ eidx,
                      const float* __restrict__ b1, const float* __restrict__ b2,
                      const float* __restrict__ bs, const float* __restrict__ bv,
                      const float* __restrict__ centers, const float* __restrict__ widths,
                      float* __restrict__ out_s, float* __restrict__ out_v, int E) {
    extern __shared__ char smem[];
    uint32_t* A32 = (uint32_t*)smem;                    // [128][164] bf16 pairs
    int* dstS = (int*)(smem + DST_OFF);
    float* dirS = (float*)(smem + DIR_OFF);
    const uint32_t Abase = smem_u32(smem);

    const int tid = threadIdx.x;
    const int wid = tid >> 5;
    const int lane = tid & 31;
    const int g = lane >> 2;
    const int tig = lane & 3;
    const int quad = lane >> 3;
    const int rowin = lane & 7;
    const int warp_m = wid & 3;     // 4 M-warps x 32 rows
    const int warp_n = wid >> 2;    // 8 N-warps x 32 cols
    const int m0 = warp_m * 32;
    const int n0 = warp_n * 32;

    const int is64 = g_idx64;
    const long long e0 = (long long)blockIdx.x * TILE_E;

    // ---- prologue: stage chunk 0 into ring slot 0 (group 1) ----
    {
        const __nv_bfloat16* w; int c0, Kl;
        chunk_src(0, w, c0, Kl);
#pragma unroll
        for (int u = 0; u < 2; ++u) {
            int unit = tid + u * 1024;
            int row = unit >> 3, sub = unit & 7;
            cpasync16(Abase + A_BYTES + row * BROW_BYTES + sub * 16,
                      (const char*)(w + (size_t)row * Kl + c0) + sub * 16);
        }
        asm volatile("cp.async.commit_group;" ::: "memory");
    }

    // ---- build A + meta: 8 threads per edge, s rows via cp.async (group 2) ----
    {
        const int m = tid >> 3;
        const int c = tid & 7;
        const bool valid = (e0 + m) < (long long)E;
        if (valid) {
            long long srcI = load_idx(eidx, e0 + m, is64);
            long long dstI = load_idx(eidx, (long long)E + e0 + m, is64);
            long long node = (c < 4) ? srcI : dstI;
            // 64B of the bf16 node row via 4x cp.async
            const char* src = (const char*)(g_sbf + node * FDIM) + (c & 3) * 64;
            uint32_t dst = Abase + (uint32_t)m * AROW_BYTES + (uint32_t)c * 64;
            cpasync16(dst, src);
            cpasync16(dst + 16, src + 16);
            cpasync16(dst + 32, src + 32);
            cpasync16(dst + 48, src + 48);
            if (c == 0) {
                float rx = pos[dstI * 3 + 0] - pos[srcI * 3 + 0];
                float ry = pos[dstI * 3 + 1] - pos[srcI * 3 + 1];
                float rz = pos[dstI * 3 + 2] - pos[srcI * 3 + 2];
                float d2 = rx * rx + ry * ry + rz * rz;
                float dist = sqrtf(d2);
                float inv = (d2 > 0.f) ? (1.0f / dist) : 0.0f;
                dstS[m] = (int)dstI;
                dirS[m * 3 + 0] = rx * inv;
                dirS[m * 3 + 1] = ry * inv;
                dirS[m * 3 + 2] = rz * inv;
            } else if (c == 7) {
                float rx = pos[dstI * 3 + 0] - pos[srcI * 3 + 0];
                float ry = pos[dstI * 3 + 1] - pos[srcI * 3 + 1];
                float rz = pos[dstI * 3 + 2] - pos[srcI * 3 + 2];
                float dist = sqrtf(rx * rx + ry * ry + rz * rz);
                uint32_t* Ar = A32 + m * APAIRS + 128;   // rbf pairs 128..137 + pad
#pragma unroll
                for (int j = 0; j < 10; ++j) {
                    float t0 = (dist - __ldg(centers + 2 * j)) /
                               (__ldg(widths + 2 * j) + 1e-8f);
                    float t1 = (dist - __ldg(centers + 2 * j + 1)) /
                               (__ldg(widths + 2 * j + 1) + 1e-8f);
                    Ar[j] = packbf(__expf(-t0 * t0), __expf(-t1 * t1));
                }
#pragma unroll
                for (int j = 10; j < 36; ++j) Ar[j] = 0;
            }
        } else {
            // zero this edge row (tail tile only)
            uint32_t* Arow = A32 + m * APAIRS + c * 16;
#pragma unroll
            for (int q = 0; q < 16; ++q) Arow[q] = 0;
            if (c == 0) dstS[m] = -1;
            if (c == 7) {
                uint32_t* Ar = A32 + m * APAIRS + 128;
#pragma unroll
                for (int j = 0; j < 36; ++j) Ar[j] = 0;
            }
        }
        asm volatile("cp.async.commit_group;" ::: "memory");  // all threads: A group
    }
    __syncthreads();   // dstS/dirS/rbf visible (cp.async data gated by wait_group below)

    float acc[2][4][4];
    int gc = 0;

#pragma unroll 1
    for (int L = 0; L < 3; ++L) {
        const int nch = (L == 0) ? 5 : 4;

#pragma unroll
        for (int mb = 0; mb < 2; ++mb)
#pragma unroll
            for (int t = 0; t < 4; ++t)
#pragma unroll
                for (int i = 0; i < 4; ++i) acc[mb][t][i] = 0.f;

#pragma unroll 1
        for (int c = 0; c < nch; ++c) {
            const int gcl = gc;
            const int c0 = c * 64;
            if (gcl + 1 < NCHUNK_TOT) {
                const __nv_bfloat16* w; int nc0, nKl;
                chunk_src(gcl + 1, w, nc0, nKl);
                uint32_t slot = Abase + A_BYTES + ((gcl + 1) % NSTAGE) * B_BYTES;
#pragma unroll
                for (int u = 0; u < 2; ++u) {
                    int unit = tid + u * 1024;
                    int row = unit >> 3, sub = unit & 7;
                    cpasync16(slot + row * BROW_BYTES + sub * 16,
                              (const char*)(w + (size_t)row * nKl + nc0) + sub * 16);
                }
                asm volatile("cp.async.commit_group;" ::: "memory");
                asm volatile("cp.async.wait_group 1;" ::: "memory");
            } else {
                asm volatile("cp.async.wait_group 0;" ::: "memory");
            }
            __syncthreads();   // publish chunk gcl (+ A data on first iteration)

            const uint32_t Bc = Abase + A_BYTES + (gcl % NSTAGE) * B_BYTES;
#pragma unroll
            for (int ks = 0; ks < 4; ++ks) {
                const int KPa = (c0 >> 1) + ks * 8;
                const int KB = ks * 8;
                uint32_t afr[2][4];
#pragma unroll
                for (int mb = 0; mb < 2; ++mb) {
                    int row = m0 + mb * 16 + (quad & 1) * 8 + rowin;
                    int kp = KPa + (quad >> 1) * 4;
                    ldm_x4(afr[mb], Abase + (uint32_t)(row * APAIRS + kp) * 4u);
                }
#pragma unroll
                for (int tp = 0; tp < 2; ++tp) {
                    uint32_t bfr[4];
                    int n = n0 + tp * 16 + (quad >> 1) * 8 + rowin;
                    int kp = KB + (quad & 1) * 4;
                    ldm_x4(bfr, Bc + (uint32_t)(n * 36 + kp) * 4u);
#pragma unroll
                    for (int mb = 0; mb < 2; ++mb) {
                        mma16816(acc[mb][2 * tp], afr[mb][0], afr[mb][1], afr[mb][2],
                                 afr[mb][3], bfr[0], bfr[1]);
                        mma16816(acc[mb][2 * tp + 1], afr[mb][0], afr[mb][1], afr[mb][2],
                                 afr[mb][3], bfr[2], bfr[3]);
                    }
                }
            }
            gc++;
        }
        __syncthreads();   // layer compute done before A overwrite / scatter

        if (L < 2) {
            const float* bias = (L == 0) ? b1 : b2;
#pragma unroll
            for (int mb = 0; mb < 2; ++mb) {
                const int r0 = m0 + mb * 16 + g;
#pragma unroll
                for (int t = 0; t < 4; ++t) {
                    const int col = n0 + t * 8 + tig * 2;
                    float bb0 = __ldg(bias + col);
                    float bb1 = __ldg(bias + col + 1);
                    const int pr = col >> 1;
                    A32[r0 * APAIRS + pr] =
                        packbf(silu(acc[mb][t][0] + bb0), silu(acc[mb][t][1] + bb1));
                    A32[(r0 + 8) * APAIRS + pr] =
                        packbf(silu(acc[mb][t][2] + bb0), silu(acc[mb][t][3] + bb1));
                }
            }
            // next chunk iteration's __syncthreads publishes these A writes
        } else {
            // scatter: warp_n 0-3 -> ds (cols 0..127); warp_n 4-7 -> dv
#pragma unroll
            for (int mb = 0; mb < 2; ++mb) {
                const int r0 = m0 + mb * 16 + g, r1 = r0 + 8;
                const int d0 = dstS[r0], d1 = dstS[r1];
                if (n0 < 128) {
#pragma unroll
                    for (int t = 0; t < 4; ++t) {
                        const int col = n0 + t * 8 + tig * 2;
                        float bb0 = __ldg(bs + col), bb1 = __ldg(bs + col + 1);
                        if (d0 >= 0)
                            red2(out_s + (long long)d0 * FDIM + col, acc[mb][t][0] + bb0,
                                 acc[mb][t][1] + bb1);
                        if (d1 >= 0)
                            red2(out_s + (long long)d1 * FDIM + col, acc[mb][t][2] + bb0,
                                 acc[mb][t][3] + bb1);
                    }
                } else {
                    float dx0 = dirS[r0 * 3], dy0 = dirS[r0 * 3 + 1], dz0 = dirS[r0 * 3 + 2];
                    float dx1 = dirS[r1 * 3], dy1 = dirS[r1 * 3 + 1], dz1 = dirS[r1 * 3 + 2];
#pragma unroll
                    for (int t = 0; t < 4; ++t) {
                        const int col = n0 - 128 + t * 8 + tig * 2;
                        float bb0 = __ldg(bv + col), bb1 = __ldg(bv + col + 1);
                        if (d0 >= 0) {
                            float v0 = acc[mb][t][0] + bb0, v1 = acc[mb][t][1] + bb1;
                            float* vb = out_v + (long long)d0 * 3 * FDIM + col;
                            red2(vb, dx0 * v0, dx0 * v1);
                            red2(vb + FDIM, dy0 * v0, dy0 * v1);
                            red2(vb + 2 * FDIM, dz0 * v0, dz0 * v1);
                        }
                        if (d1 >= 0) {
                            float v0 = acc[mb][t][2] + bb0, v1 = acc[mb][t][3] + bb1;
                            float* vb = out_v + (long long)d1 * 3 * FDIM + col;
                            red2(vb, dx1 * v0, dx1 * v1);
                            red2(vb + FDIM, dy1 * v0, dy1 * v1);
                            red2(vb + 2 * FDIM, dz1 * v0, dz1 * v1);
                        }
                    }
                }
            }
        }
    }
}

// ---------------- launcher ----------------
extern "C" void kernel_launch(void* const* d_in, const int* in_sizes, int n_in,
                              void* d_out, int out_size) {
    const float* s       = (const float*)d_in[0];
    const float* v       = (const float*)d_in[1];
    const float* pos     = (const float*)d_in[2];
    const void*  eidx    = d_in[3];
    const float* W1      = (const float*)d_in[4];
    const float* b1      = (const float*)d_in[5];
    const float* W2      = (const float*)d_in[6];
    const float* b2      = (const float*)d_in[7];
    const float* Ws      = (const float*)d_in[8];
    const float* bs      = (const float*)d_in[9];
    const float* Wv      = (const float*)d_in[10];
    const float* bv      = (const float*)d_in[11];
    const float* centers = (const float*)d_in[12];
    const float* widths  = (const float*)d_in[13];

    int N = in_sizes[0] / FDIM;
    int E = in_sizes[3] / 2;

    float* out_s = (float*)d_out;
    float* out_v = out_s + (long long)N * FDIM;

    detect_idx_kernel<<<1, 256>>>((const int*)eidx);

    int ns4 = N * FDIM / 4;
    int nv4 = N * 3 * FDIM / 4;
    init_out_kernel<<<1024, 256>>>((const float4*)s, (const float4*)v, (float4*)d_out, ns4, nv4);

    prep_weights<<<512, 256>>>(W1, W2, Ws, Wv, s, N * FDIM);

    cudaFuncSetAttribute(painn_mma_kernel, cudaFuncAttributeMaxDynamicSharedMemorySize,
                         SMEM_TOTAL);

    int grid = (E + TILE_E - 1) / TILE_E;
    painn_mma_kernel<<<grid, NTHREADS, SMEM_TOTAL>>>(pos, eidx, b1, b2, bs, bv, centers,
                                                     widths, out_s, out_v, E);
}

// round 16
// speedup vs baseline: 1.1986x; 1.0276x over previous
#include <cuda_runtime.h>
#include <cuda_bf16.h>
#include <cstdint>
#include <math.h>

// PaiNN interaction — fused HMMA bf16 kernel, round 16.
// R15 crashed: B stride 136 broke cp.async 16B alignment. Fix: stride 144, and
// recover smem via K1 pad 320->288 (A row 592B, conflict-free: 592%128=80) and
// meta folded into A-row dead pairs. 2 CTAs/SM (111.6KB each), TILE_E=64.
//
// Inputs: 0 s [N,128] f32, 1 v [N,3,128] f32, 2 pos [N,3] f32, 3 edge_index [2,E],
// 4 W1 [276,256], 5 b1, 6 W2, 7 b2, 8 Ws, 9 bs, 10 Wv, 11 bv, 12 centers, 13 widths
// Output: concat(s_out [N,128], v_out [N,3,128]) f32.

#define FDIM 128
#define NRBF 20
#define IN_DIM 276
#define K1 288               // layer-1 K padded (4x64 + 1x32 chunks)
#define K23 256
#define TILE_E 64
#define NTHREADS 512
#define NCHUNK_TOT 13        // 5 + 4 + 4
#define NMAX 50176

#define APAIRS 148           // u32 per A row; 592B stride, %128=80 -> conflict-free
#define AROW_BYTES 592       // multiple of 16
#define A_BYTES (TILE_E * AROW_BYTES)            // 37888
#define M_DIRX 144           // meta pairs inside each A row
#define M_DIRY 145
#define M_DIRZ 146
#define M_DST  147
#define BROW_BYTES 144       // 16B-multiple; %128=16 -> conflict-free
#define B_BYTES (256 * BROW_BYTES)               // 36864
#define SMEM_TOTAL (A_BYTES + 2 * B_BYTES)       // 111616 -> 2 CTAs/SM

// ---------------- device globals ----------------
__device__ __align__(16) __nv_bfloat16 g_W1T[256 * K1];    // [n][k], k>=276 zero
__device__ __align__(16) __nv_bfloat16 g_W2T[256 * K23];
__device__ __align__(16) __nv_bfloat16 g_WsvT[256 * K23];  // n<128 Ws, n>=128 Wv
__device__ __align__(16) __nv_bfloat16 g_sbf[NMAX * FDIM]; // bf16 copy of s
__device__ int g_idx64;

// ---------------- helpers ----------------
__device__ __forceinline__ uint32_t smem_u32(const void* p) {
    uint32_t a;
    asm("{ .reg .u64 t; cvta.to.shared.u64 t, %1; cvt.u32.u64 %0, t; }" : "=r"(a) : "l"(p));
    return a;
}
__device__ __forceinline__ uint32_t packbf(float a, float b) {
    __nv_bfloat162 h = __floats2bfloat162_rn(a, b);
    return *reinterpret_cast<uint32_t*>(&h);
}
__device__ __forceinline__ float silu(float x) { return x / (1.0f + __expf(-x)); }

__device__ __forceinline__ void mma16816(float c[4], uint32_t a0, uint32_t a1, uint32_t a2,
                                         uint32_t a3, uint32_t b0, uint32_t b1) {
    asm volatile(
        "mma.sync.aligned.m16n8k16.row.col.f32.bf16.bf16.f32 "
        "{%0,%1,%2,%3}, {%4,%5,%6,%7}, {%8,%9}, {%0,%1,%2,%3};"
        : "+f"(c[0]), "+f"(c[1]), "+f"(c[2]), "+f"(c[3])
        : "r"(a0), "r"(a1), "r"(a2), "r"(a3), "r"(b0), "r"(b1));
}

__device__ __forceinline__ void ldm_x4(uint32_t r[4], uint32_t addr) {
    asm volatile("ldmatrix.sync.aligned.m8n8.x4.shared.b16 {%0,%1,%2,%3}, [%4];"
                 : "=r"(r[0]), "=r"(r[1]), "=r"(r[2]), "=r"(r[3]) : "r"(addr));
}

__device__ __forceinline__ void cpasync16(uint32_t dst, const void* src) {
    asm volatile("cp.async.cg.shared.global [%0], [%1], 16;" :: "r"(dst), "l"(src)
                 : "memory");
}

__device__ __forceinline__ void red2(float* p, float a, float b) {
    asm volatile("red.global.add.v2.f32 [%0], {%1, %2};" :: "l"(p), "f"(a), "f"(b) : "memory");
}

__device__ __forceinline__ long long load_idx(const void* p, long long i, int is64) {
    if (is64) return ((const long long*)p)[i];
    return (long long)((const int*)p)[i];
}

// chunk index -> weight matrix / element offset / row stride / chunk width (elems)
__device__ __forceinline__ void chunk_src(int gc, const __nv_bfloat16*& w, int& c0,
                                          int& Kl, int& kw) {
    if (gc < 5)      { w = g_W1T;  c0 = gc * 64;       Kl = K1;  kw = (gc == 4) ? 32 : 64; }
    else if (gc < 9) { w = g_W2T;  c0 = (gc - 5) * 64; Kl = K23; kw = 64; }
    else             { w = g_WsvT; c0 = (gc - 9) * 64; Kl = K23; kw = 64; }
}

// stage one B chunk (256 rows x kw*2 bytes) into a ring slot; 512 threads
__device__ __forceinline__ void stage_chunk(uint32_t slotbase, const __nv_bfloat16* w,
                                            int c0, int Kl, int kw, int tid) {
    if (kw == 64) {          // 128B rows: 2048 16B-units, 4/thread
#pragma unroll
        for (int u = 0; u < 4; ++u) {
            int unit = tid + u * 512;
            int row = unit >> 3, sub = unit & 7;
            cpasync16(slotbase + row * BROW_BYTES + sub * 16,
                      (const char*)(w + (size_t)row * Kl + c0) + sub * 16);
        }
    } else {                 // 64B rows: 1024 16B-units, 2/thread
#pragma unroll
        for (int u = 0; u < 2; ++u) {
            int unit = tid + u * 512;
            int row = unit >> 2, sub = unit & 3;
            cpasync16(slotbase + row * BROW_BYTES + sub * 16,
                      (const char*)(w + (size_t)row * Kl + c0) + sub * 16);
        }
    }
    asm volatile("cp.async.commit_group;" ::: "memory");
}

// ---------------- small helper kernels ----------------
__global__ void detect_idx_kernel(const int* __restrict__ idx32) {
    __shared__ int nz;
    if (threadIdx.x == 0) nz = 0;
    __syncthreads();
    int v = idx32[2 * threadIdx.x + 1];
    if (v != 0) atomicOr(&nz, 1);
    __syncthreads();
    if (threadIdx.x == 0) g_idx64 = (nz == 0) ? 1 : 0;
}

__global__ void init_out_kernel(const float4* __restrict__ s, const float4* __restrict__ v,
                                float4* __restrict__ out, int ns4, int nv4) {
    int stride = gridDim.x * blockDim.x;
    for (int i = blockIdx.x * blockDim.x + threadIdx.x; i < ns4; i += stride) out[i] = s[i];
    for (int i = blockIdx.x * blockDim.x + threadIdx.x; i < nv4; i += stride)
        out[ns4 + i] = v[i];
}

__global__ void prep_weights(const float* __restrict__ W1, const float* __restrict__ W2,
                             const float* __restrict__ Ws, const float* __restrict__ Wv,
                             const float* __restrict__ s, int nselem) {
    const int t1 = 256 * K1;
    const int t2 = t1 + 256 * K23;
    const int t3 = t2 + 256 * K23;
    const int t4 = t3 + nselem;
    int stride = gridDim.x * blockDim.x;
    for (int idx = blockIdx.x * blockDim.x + threadIdx.x; idx < t4; idx += stride) {
        if (idx < t1) {
            int n = idx / K1, k = idx % K1;
            g_W1T[idx] = __float2bfloat16((k < IN_DIM) ? W1[k * 256 + n] : 0.0f);
        } else if (idx < t2) {
            int r = idx - t1;
            int n = r / K23, k = r % K23;
            g_W2T[r] = __float2bfloat16(W2[k * 256 + n]);
        } else if (idx < t3) {
            int r = idx - t2;
            int n = r / K23, k = r % K23;
            float val = (n < FDIM) ? Ws[k * FDIM + n] : Wv[k * FDIM + (n - FDIM)];
            g_WsvT[r] = __float2bfloat16(val);
        } else {
            int r = idx - t3;
            g_sbf[r] = __float2bfloat16(s[r]);
        }
    }
}

// ---------------- main fused kernel ----------------
__global__ __launch_bounds__(NTHREADS, 2)
void painn_mma_kernel(const float* __restrict__ pos,
                      const void* __restrict__ eidx,
                      const float* __restrict__ b1, const float* __restrict__ b2,
                      const float* __restrict__ bs, const float* __restrict__ bv,
                      const float* __restrict__ centers, const float* __restrict__ widths,
                      float* __restrict__ out_s, float* __restrict__ out_v, int E) {
    extern __shared__ char smem[];
    uint32_t* A32 = (uint32_t*)smem;                    // [64][148] u32
    const uint32_t Abase = smem_u32(smem);

    const int tid = threadIdx.x;
    const int wid = tid >> 5;
    const int lane = tid & 31;
    const int g = lane >> 2;
    const int tig = lane & 3;
    const int quad = lane >> 3;
    const int rowin = lane & 7;
    const int warp_m = wid & 1;     // 2 M-warps x 32 rows
    const int warp_n = wid >> 1;    // 8 N-warps x 32 cols
    const int m0 = warp_m * 32;
    const int n0 = warp_n * 32;

    const int is64 = g_idx64;
    const long long e0 = (long long)blockIdx.x * TILE_E;

    // ---- prologue: stage chunk 0 into ring slot 0 ----
    {
        const __nv_bfloat16* w; int c0, Kl, kw;
        chunk_src(0, w, c0, Kl, kw);
        stage_chunk(Abase + A_BYTES, w, c0, Kl, kw, tid);
    }

    // ---- build A + meta: 8 threads per edge (512 thr -> 64 edges) ----
    {
        const int m = tid >> 3;
        const int c = tid & 7;
        const bool valid = (e0 + m) < (long long)E;
        uint32_t* Arow = A32 + m * APAIRS;
        if (valid) {
            long long srcI = load_idx(eidx, e0 + m, is64);
            long long dstI = load_idx(eidx, (long long)E + e0 + m, is64);
            long long node = (c < 4) ? srcI : dstI;
            const char* src = (const char*)(g_sbf + node * FDIM) + (c & 3) * 64;
            uint32_t dst = Abase + (uint32_t)m * AROW_BYTES + (uint32_t)c * 64;
            cpasync16(dst, src);
            cpasync16(dst + 16, src + 16);
            cpasync16(dst + 32, src + 32);
            cpasync16(dst + 48, src + 48);
            if (c == 0) {
                float rx = pos[dstI * 3 + 0] - pos[srcI * 3 + 0];
                float ry = pos[dstI * 3 + 1] - pos[srcI * 3 + 1];
                float rz = pos[dstI * 3 + 2] - pos[srcI * 3 + 2];
                float d2 = rx * rx + ry * ry + rz * rz;
                float dist = sqrtf(d2);
                float inv = (d2 > 0.f) ? (1.0f / dist) : 0.0f;
                Arow[M_DIRX] = __float_as_uint(rx * inv);
                Arow[M_DIRY] = __float_as_uint(ry * inv);
                Arow[M_DIRZ] = __float_as_uint(rz * inv);
                Arow[M_DST]  = (uint32_t)(int)dstI;
            } else if (c == 7) {
                float rx = pos[dstI * 3 + 0] - pos[srcI * 3 + 0];
                float ry = pos[dstI * 3 + 1] - pos[srcI * 3 + 1];
                float rz = pos[dstI * 3 + 2] - pos[srcI * 3 + 2];
                float dist = sqrtf(rx * rx + ry * ry + rz * rz);
#pragma unroll
                for (int j = 0; j < 10; ++j) {   // rbf pairs 128..137
                    float t0 = (dist - __ldg(centers + 2 * j)) /
                               (__ldg(widths + 2 * j) + 1e-8f);
                    float t1 = (dist - __ldg(centers + 2 * j + 1)) /
                               (__ldg(widths + 2 * j + 1) + 1e-8f);
                    Arow[128 + j] = packbf(__expf(-t0 * t0), __expf(-t1 * t1));
                }
#pragma unroll
                for (int j = 138; j < 144; ++j) Arow[j] = 0;   // K pad to 288
            }
        } else {
            // tail tile: zero data pairs, mark dst invalid
#pragma unroll
            for (int q = 0; q < 16; ++q) Arow[c * 16 + q] = 0;
            if (c == 0) Arow[M_DST] = (uint32_t)(-1);
            if (c == 7) {
#pragma unroll
                for (int j = 128; j < 144; ++j) Arow[j] = 0;
                Arow[M_DIRX] = 0; Arow[M_DIRY] = 0; Arow[M_DIRZ] = 0;
            }
        }
        asm volatile("cp.async.commit_group;" ::: "memory");
    }
    __syncthreads();

    float acc[2][4][4];
    int gc = 0;

#pragma unroll 1
    for (int L = 0; L < 3; ++L) {
        const int nch = (L == 0) ? 5 : 4;

#pragma unroll
        for (int mb = 0; mb < 2; ++mb)
#pragma unroll
            for (int t = 0; t < 4; ++t)
#pragma unroll
                for (int i = 0; i < 4; ++i) acc[mb][t][i] = 0.f;

#pragma unroll 1
        for (int c = 0; c < nch; ++c) {
            const int gcl = gc;
            const __nv_bfloat16* w; int c0, Kl, kw;
            chunk_src(gcl, w, c0, Kl, kw);

            asm volatile("cp.async.wait_group 0;" ::: "memory");  // chunk gcl (+A) landed
            __syncthreads();   // publish chunk gcl; retire other slot's consumers

            // stage NEXT chunk into the other slot (drains under compute; the
            // co-resident CTA's MMAs cover this CTA's wait)
            if (gcl + 1 < NCHUNK_TOT) {
                const __nv_bfloat16* nw; int nc0, nKl, nkw;
                chunk_src(gcl + 1, nw, nc0, nKl, nkw);
                stage_chunk(Abase + A_BYTES + ((gcl + 1) & 1) * B_BYTES, nw, nc0, nKl, nkw,
                            tid);
            }

            const uint32_t Bc = Abase + A_BYTES + (gcl & 1) * B_BYTES;
            const int nks = kw >> 4;   // 4 or 2
#pragma unroll 1
            for (int ks = 0; ks < nks; ++ks) {
                const int KPa = (c0 >> 1) + ks * 8;
                const int KBb = ks * 32;
                uint32_t afr[2][4];
#pragma unroll
                for (int mb = 0; mb < 2; ++mb) {
                    int row = m0 + mb * 16 + (quad & 1) * 8 + rowin;
                    int kp = KPa + (quad >> 1) * 4;
                    ldm_x4(afr[mb], Abase + (uint32_t)row * AROW_BYTES + (uint32_t)kp * 4u);
                }
#pragma unroll
                for (int tp = 0; tp < 2; ++tp) {
                    uint32_t bfr[4];
                    int n = n0 + tp * 16 + (quad >> 1) * 8 + rowin;
                    ldm_x4(bfr, Bc + (uint32_t)n * BROW_BYTES + KBb + (quad & 1) * 16);
#pragma unroll
                    for (int mb = 0; mb < 2; ++mb) {
                        mma16816(acc[mb][2 * tp], afr[mb][0], afr[mb][1], afr[mb][2],
                                 afr[mb][3], bfr[0], bfr[1]);
                        mma16816(acc[mb][2 * tp + 1], afr[mb][0], afr[mb][1], afr[mb][2],
                                 afr[mb][3], bfr[2], bfr[3]);
                    }
                }
            }
            gc++;
        }
        __syncthreads();   // layer compute done before A overwrite / scatter

        if (L < 2) {
            const float* bias = (L == 0) ? b1 : b2;
#pragma unroll
            for (int mb = 0; mb < 2; ++mb) {
                const int r0 = m0 + mb * 16 + g;
#pragma unroll
                for (int t = 0; t < 4; ++t) {
                    const int col = n0 + t * 8 + tig * 2;
                    float bb0 = __ldg(bias + col);
                    float bb1 = __ldg(bias + col + 1);
                    const int pr = col >> 1;
                    A32[r0 * APAIRS + pr] =
                        packbf(silu(acc[mb][t][0] + bb0), silu(acc[mb][t][1] + bb1));
                    A32[(r0 + 8) * APAIRS + pr] =
                        packbf(silu(acc[mb][t][2] + bb0), silu(acc[mb][t][3] + bb1));
                }
            }
            // next chunk iteration's __syncthreads publishes these A writes
        } else {
            // scatter: warp_n 0-3 -> ds (cols 0..127); warp_n 4-7 -> dv
#pragma unroll
            for (int mb = 0; mb < 2; ++mb) {
                const int r0 = m0 + mb * 16 + g, r1 = r0 + 8;
                const int d0 = (int)A32[r0 * APAIRS + M_DST];
                const int d1 = (int)A32[r1 * APAIRS + M_DST];
                if (n0 < 128) {
#pragma unroll
                    for (int t = 0; t < 4; ++t) {
                        const int col = n0 + t * 8 + tig * 2;
                        float bb0 = __ldg(bs + col), bb1 = __ldg(bs + col + 1);
                        if (d0 >= 0)
                            red2(out_s + (long long)d0 * FDIM + col, acc[mb][t][0] + bb0,
                                 acc[mb][t][1] + bb1);
                        if (d1 >= 0)
                            red2(out_s + (long long)d1 * FDIM + col, acc[mb][t][2] + bb0,
                                 acc[mb][t][3] + bb1);
                    }
                } else {
                    float dx0 = __uint_as_float(A32[r0 * APAIRS + M_DIRX]);
                    float dy0 = __uint_as_float(A32[r0 * APAIRS + M_DIRY]);
                    float dz0 = __uint_as_float(A32[r0 * APAIRS + M_DIRZ]);
                    float dx1 = __uint_as_float(A32[r1 * APAIRS + M_DIRX]);
                    float dy1 = __uint_as_float(A32[r1 * APAIRS + M_DIRY]);
                    float dz1 = __uint_as_float(A32[r1 * APAIRS + M_DIRZ]);
#pragma unroll
                    for (int t = 0; t < 4; ++t) {
                        const int col = n0 - 128 + t * 8 + tig * 2;
                        float bb0 = __ldg(bv + col), bb1 = __ldg(bv + col + 1);
                        if (d0 >= 0) {
                            float v0 = acc[mb][t][0] + bb0, v1 = acc[mb][t][1] + bb1;
                            float* vb = out_v + (long long)d0 * 3 * FDIM + col;
                            red2(vb, dx0 * v0, dx0 * v1);
                            red2(vb + FDIM, dy0 * v0, dy0 * v1);
                            red2(vb + 2 * FDIM, dz0 * v0, dz0 * v1);
                        }
                        if (d1 >= 0) {
                            float v0 = acc[mb][t][2] + bb0, v1 = acc[mb][t][3] + bb1;
                            float* vb = out_v + (long long)d1 * 3 * FDIM + col;
                            red2(vb, dx1 * v0, dx1 * v1);
                            red2(vb + FDIM, dy1 * v0, dy1 * v1);
                            red2(vb + 2 * FDIM, dz1 * v0, dz1 * v1);
                        }
                    }
                }
            }
        }
    }
}

// ---------------- launcher ----------------
extern "C" void kernel_launch(void* const* d_in, const int* in_sizes, int n_in,
                              void* d_out, int out_size) {
    const float* s       = (const float*)d_in[0];
    const float* v       = (const float*)d_in[1];
    const float* pos     = (const float*)d_in[2];
    const void*  eidx    = d_in[3];
    const float* W1      = (const float*)d_in[4];
    const float* b1      = (const float*)d_in[5];
    const float* W2      = (const float*)d_in[6];
    const float* b2      = (const float*)d_in[7];
    const float* Ws      = (const float*)d_in[8];
    const float* bs      = (const float*)d_in[9];
    const float* Wv      = (const float*)d_in[10];
    const float* bv      = (const float*)d_in[11];
    const float* centers = (const float*)d_in[12];
    const float* widths  = (const float*)d_in[13];

    int N = in_sizes[0] / FDIM;
    int E = in_sizes[3] / 2;

    float* out_s = (float*)d_out;
    float* out_v = out_s + (long long)N * FDIM;

    detect_idx_kernel<<<1, 256>>>((const int*)eidx);

    int ns4 = N * FDIM / 4;
    int nv4 = N * 3 * FDIM / 4;
    init_out_kernel<<<1024, 256>>>((const float4*)s, (const float4*)v, (float4*)d_out, ns4, nv4);

    prep_weights<<<512, 256>>>(W1, W2, Ws, Wv, s, N * FDIM);

    cudaFuncSetAttribute(painn_mma_kernel, cudaFuncAttributeMaxDynamicSharedMemorySize,
                         SMEM_TOTAL);

    int grid = (E + TILE_E - 1) / TILE_E;
    painn_mma_kernel<<<grid, NTHREADS, SMEM_TOTAL>>>(pos, eidx, b1, b2, bs, bv, centers,
                                                     widths, out_s, out_v, E);
}

// round 17
// speedup vs baseline: 1.2353x; 1.0306x over previous
#include <cuda_runtime.h>
#include <cuda_bf16.h>
#include <cstdint>
#include <math.h>

// PaiNN interaction — round 17: algebraic restructuring.
// Layer-1's s@W1 terms are per-NODE: precompute pre_a=s@W1[0:128], pre_b=s@W1[128:256]
// once (bf16 [N,512] table, MMA prep kernel), so per-edge layer 1 is just a K=32
// rbf MMA + gathered add. Per-edge K-work 800->544, chunks 13->9, no s-gather.
// Core loop/scatter = round-16 (2 CTAs/SM, 2-slot ring, wait0->sync->stage->compute).
//
// Inputs: 0 s, 1 v, 2 pos, 3 edge_index, 4 W1 [276,256], 5 b1, 6 W2, 7 b2,
// 8 Ws, 9 bs, 10 Wv, 11 bv, 12 centers, 13 widths
// Output: concat(s_out [N,128], v_out [N,3,128]) f32.

#define FDIM 128
#define NRBF 20
#define IN_DIM 276
#define K23 256
#define TILE_E 64
#define NTHREADS 512
#define NCHUNK_TOT 9         // 1 (rbf,K=32) + 4 (W2) + 4 (Wsv)
#define NMAX 50176

#define APAIRS 140           // u32/row; 140%32=4 -> ldmatrix conflict-free; 560B stride
#define AROW_BYTES 560
#define A_BYTES (TILE_E * AROW_BYTES)            // 35840
#define M_SRC 128
#define M_DST 129
#define M_DIRX 130
#define M_DIRY 131
#define M_DIRZ 132
#define BROW_BYTES 144       // 36 u32; 36%32=4 -> conflict-free
#define B_BYTES (256 * BROW_BYTES)               // 36864
#define SMEM_TOTAL (A_BYTES + 2 * B_BYTES)       // 109568 -> 2 CTAs/SM

// prep_pre kernel geometry
#define P_APAIRS 68          // 68%32=4 -> conflict-free; 272B stride
#define P_AROW_BYTES 272
#define P_ABYTES (64 * P_AROW_BYTES)             // 17408
#define P_SMEM (P_ABYTES + 2 * B_BYTES)          // 91136

// ---------------- device globals ----------------
__device__ __align__(16) __nv_bfloat16 g_W2T[256 * K23];
__device__ __align__(16) __nv_bfloat16 g_WsvT[256 * K23];   // n<128 Ws, else Wv
__device__ __align__(16) __nv_bfloat16 g_W1rbfT[256 * 32];  // [n][k] rbf rows of W1, pad 32
__device__ __align__(16) __nv_bfloat16 g_W1cat[512 * 128];  // [j][k]: j<256 W1[k][j], else W1[128+k][j-256]
__device__ __align__(16) __nv_bfloat16 g_sbf[NMAX * FDIM];
__device__ __align__(16) __nv_bfloat16 g_pre[(size_t)NMAX * 512];  // [node][pre_a|pre_b]
__device__ int g_idx64;

// ---------------- helpers ----------------
__device__ __forceinline__ uint32_t smem_u32(const void* p) {
    uint32_t a;
    asm("{ .reg .u64 t; cvta.to.shared.u64 t, %1; cvt.u32.u64 %0, t; }" : "=r"(a) : "l"(p));
    return a;
}
__device__ __forceinline__ uint32_t packbf(float a, float b) {
    __nv_bfloat162 h = __floats2bfloat162_rn(a, b);
    return *reinterpret_cast<uint32_t*>(&h);
}
__device__ __forceinline__ float silu(float x) { return x / (1.0f + __expf(-x)); }

__device__ __forceinline__ void mma16816(float c[4], uint32_t a0, uint32_t a1, uint32_t a2,
                                         uint32_t a3, uint32_t b0, uint32_t b1) {
    asm volatile(
        "mma.sync.aligned.m16n8k16.row.col.f32.bf16.bf16.f32 "
        "{%0,%1,%2,%3}, {%4,%5,%6,%7}, {%8,%9}, {%0,%1,%2,%3};"
        : "+f"(c[0]), "+f"(c[1]), "+f"(c[2]), "+f"(c[3])
        : "r"(a0), "r"(a1), "r"(a2), "r"(a3), "r"(b0), "r"(b1));
}

__device__ __forceinline__ void ldm_x4(uint32_t r[4], uint32_t addr) {
    asm volatile("ldmatrix.sync.aligned.m8n8.x4.shared.b16 {%0,%1,%2,%3}, [%4];"
                 : "=r"(r[0]), "=r"(r[1]), "=r"(r[2]), "=r"(r[3]) : "r"(addr));
}

__device__ __forceinline__ void cpasync16(uint32_t dst, const void* src) {
    asm volatile("cp.async.cg.shared.global [%0], [%1], 16;" :: "r"(dst), "l"(src)
                 : "memory");
}

__device__ __forceinline__ void red2(float* p, float a, float b) {
    asm volatile("red.global.add.v2.f32 [%0], {%1, %2};" :: "l"(p), "f"(a), "f"(b) : "memory");
}

__device__ __forceinline__ long long load_idx(const void* p, long long i, int is64) {
    if (is64) return ((const long long*)p)[i];
    return (long long)((const int*)p)[i];
}

// bf16x2 word -> two floats
__device__ __forceinline__ void unpk(uint32_t u, float& lo, float& hi) {
    lo = __uint_as_float(u << 16);
    hi = __uint_as_float(u & 0xFFFF0000u);
}

// main-kernel chunk table
__device__ __forceinline__ void chunk_src(int gc, const __nv_bfloat16*& w, int& c0,
                                          int& Kl, int& kw) {
    if (gc == 0)     { w = g_W1rbfT; c0 = 0;            Kl = 32;  kw = 32; }
    else if (gc < 5) { w = g_W2T;    c0 = (gc - 1) * 64; Kl = K23; kw = 64; }
    else             { w = g_WsvT;   c0 = (gc - 5) * 64; Kl = K23; kw = 64; }
}

// stage one B chunk (256 rows x kw*2 bytes) into a ring slot; 512 threads
__device__ __forceinline__ void stage_chunk(uint32_t slotbase, const __nv_bfloat16* w,
                                            int c0, int Kl, int kw, int tid) {
    if (kw == 64) {
#pragma unroll
        for (int u = 0; u < 4; ++u) {
            int unit = tid + u * 512;
            int row = unit >> 3, sub = unit & 7;
            cpasync16(slotbase + row * BROW_BYTES + sub * 16,
                      (const char*)(w + (size_t)row * Kl + c0) + sub * 16);
        }
    } else {   // kw == 32: 64B rows
#pragma unroll
        for (int u = 0; u < 2; ++u) {
            int unit = tid + u * 512;
            int row = unit >> 2, sub = unit & 3;
            cpasync16(slotbase + row * BROW_BYTES + sub * 16,
                      (const char*)(w + (size_t)row * Kl + c0) + sub * 16);
        }
    }
    asm volatile("cp.async.commit_group;" ::: "memory");
}

// ---------------- small helper kernels ----------------
__global__ void detect_idx_kernel(const int* __restrict__ idx32) {
    __shared__ int nz;
    if (threadIdx.x == 0) nz = 0;
    __syncthreads();
    int v = idx32[2 * threadIdx.x + 1];
    if (v != 0) atomicOr(&nz, 1);
    __syncthreads();
    if (threadIdx.x == 0) g_idx64 = (nz == 0) ? 1 : 0;
}

__global__ void init_out_kernel(const float4* __restrict__ s, const float4* __restrict__ v,
                                float4* __restrict__ out, int ns4, int nv4) {
    int stride = gridDim.x * blockDim.x;
    for (int i = blockIdx.x * blockDim.x + threadIdx.x; i < ns4; i += stride) out[i] = s[i];
    for (int i = blockIdx.x * blockDim.x + threadIdx.x; i < nv4; i += stride)
        out[ns4 + i] = v[i];
}

__global__ void prep_weights(const float* __restrict__ W1, const float* __restrict__ W2,
                             const float* __restrict__ Ws, const float* __restrict__ Wv,
                             const float* __restrict__ s, int nselem) {
    const int t1 = 256 * K23;                 // W2T
    const int t2 = t1 + 256 * K23;            // WsvT
    const int t3 = t2 + 256 * 32;             // W1rbfT
    const int t4 = t3 + 512 * 128;            // W1cat
    const int t5 = t4 + nselem;               // sbf
    int stride = gridDim.x * blockDim.x;
    for (int idx = blockIdx.x * blockDim.x + threadIdx.x; idx < t5; idx += stride) {
        if (idx < t1) {
            int n = idx >> 8, k = idx & 255;
            g_W2T[idx] = __float2bfloat16(W2[k * 256 + n]);
        } else if (idx < t2) {
            int r = idx - t1;
            int n = r >> 8, k = r & 255;
            float val = (n < FDIM) ? Ws[k * FDIM + n] : Wv[k * FDIM + (n - FDIM)];
            g_WsvT[r] = __float2bfloat16(val);
        } else if (idx < t3) {
            int r = idx - t2;
            int n = r >> 5, k = r & 31;
            g_W1rbfT[r] = __float2bfloat16((k < NRBF) ? W1[(256 + k) * 256 + n] : 0.0f);
        } else if (idx < t4) {
            int r = idx - t3;
            int j = r >> 7, k = r & 127;
            float val = (j < 256) ? W1[k * 256 + j] : W1[(128 + k) * 256 + (j - 256)];
            g_W1cat[r] = __float2bfloat16(val);
        } else {
            int r = idx - t4;
            g_sbf[r] = __float2bfloat16(s[r]);
        }
    }
}

// ---------------- pre-table GEMM: g_pre[n][0:256]=s@W1a, [256:512]=s@W1b ----------------
__global__ __launch_bounds__(NTHREADS, 2)
void prep_pre_kernel(int N) {
    extern __shared__ char smem[];
    const uint32_t Abase = smem_u32(smem);

    const int tid = threadIdx.x;
    const int wid = tid >> 5;
    const int lane = tid & 31;
    const int g = lane >> 2;
    const int tig = lane & 3;
    const int quad = lane >> 3;
    const int rowin = lane & 7;
    const int warp_m = wid & 1;
    const int warp_n = wid >> 1;
    const int m0 = warp_m * 32;
    const int n0 = warp_n * 32;

    const long long node0 = (long long)blockIdx.x * 64;

    // stage chunk 0 (half 0, k 0..63)
    stage_chunk(Abase + P_ABYTES, g_W1cat, 0, 128, 64, tid);

    // build A: 64 node rows of g_sbf (256B each) at stride 272; 1024 units, 2/thread
#pragma unroll
    for (int u = 0; u < 2; ++u) {
        int unit = tid + u * 512;
        int row = unit >> 4, sub = unit & 15;
        long long node = node0 + row;
        if (node < N) {
            cpasync16(Abase + row * P_AROW_BYTES + sub * 16,
                      (const char*)(g_sbf + node * FDIM) + sub * 16);
        } else {
            *(uint4*)(smem + row * P_AROW_BYTES + sub * 16) = make_uint4(0, 0, 0, 0);
        }
    }
    asm volatile("cp.async.commit_group;" ::: "memory");
    __syncthreads();

    float acc[2][4][4];
    int gc = 0;
#pragma unroll 1
    for (int half = 0; half < 2; ++half) {
#pragma unroll
        for (int mb = 0; mb < 2; ++mb)
#pragma unroll
            for (int t = 0; t < 4; ++t)
#pragma unroll
                for (int i = 0; i < 4; ++i) acc[mb][t][i] = 0.f;

#pragma unroll 1
        for (int c = 0; c < 2; ++c) {
            const int gcl = gc;
            const int c0 = (gcl & 1) * 64;
            asm volatile("cp.async.wait_group 0;" ::: "memory");
            __syncthreads();
            if (gcl + 1 < 4) {
                int ngc = gcl + 1;
                stage_chunk(Abase + P_ABYTES + ((ngc)&1) * B_BYTES,
                            g_W1cat + (size_t)(ngc >> 1) * 256 * 128, (ngc & 1) * 64, 128,
                            64, tid);
            }
            const uint32_t Bc = Abase + P_ABYTES + (gcl & 1) * B_BYTES;
#pragma unroll
            for (int ks = 0; ks < 4; ++ks) {
                const int KPa = (c0 >> 1) + ks * 8;
                const int KBb = ks * 32;
                uint32_t afr[2][4];
#pragma unroll
                for (int mb = 0; mb < 2; ++mb) {
                    int row = m0 + mb * 16 + (quad & 1) * 8 + rowin;
                    int kp = KPa + (quad >> 1) * 4;
                    ldm_x4(afr[mb],
                           Abase + (uint32_t)row * P_AROW_BYTES + (uint32_t)kp * 4u);
                }
#pragma unroll
                for (int tp = 0; tp < 2; ++tp) {
                    uint32_t bfr[4];
                    int n = n0 + tp * 16 + (quad >> 1) * 8 + rowin;
                    ldm_x4(bfr, Bc + (uint32_t)n * BROW_BYTES + KBb + (quad & 1) * 16);
#pragma unroll
                    for (int mb = 0; mb < 2; ++mb) {
                        mma16816(acc[mb][2 * tp], afr[mb][0], afr[mb][1], afr[mb][2],
                                 afr[mb][3], bfr[0], bfr[1]);
                        mma16816(acc[mb][2 * tp + 1], afr[mb][0], afr[mb][1], afr[mb][2],
                                 afr[mb][3], bfr[2], bfr[3]);
                    }
                }
            }
            gc++;
        }
        // write this half to g_pre (bf16)
#pragma unroll
        for (int mb = 0; mb < 2; ++mb) {
            const int r0 = m0 + mb * 16 + g, r1 = r0 + 8;
            long long nd0 = node0 + r0, nd1 = node0 + r1;
#pragma unroll
            for (int t = 0; t < 4; ++t) {
                const int col = half * 256 + n0 + t * 8 + tig * 2;
                if (nd0 < N)
                    *(uint32_t*)((char*)g_pre + ((size_t)nd0 * 512 + col) * 2) =
                        packbf(acc[mb][t][0], acc[mb][t][1]);
                if (nd1 < N)
                    *(uint32_t*)((char*)g_pre + ((size_t)nd1 * 512 + col) * 2) =
                        packbf(acc[mb][t][2], acc[mb][t][3]);
            }
        }
    }
}

// ---------------- main fused kernel ----------------
__global__ __launch_bounds__(NTHREADS, 2)
void painn_mma_kernel(const float* __restrict__ pos,
                      const void* __restrict__ eidx,
                      const float* __restrict__ b1, const float* __restrict__ b2,
                      const float* __restrict__ bs, const float* __restrict__ bv,
                      const float* __restrict__ centers, const float* __restrict__ widths,
                      float* __restrict__ out_s, float* __restrict__ out_v, int E) {
    extern __shared__ char smem[];
    uint32_t* A32 = (uint32_t*)smem;
    const uint32_t Abase = smem_u32(smem);

    const int tid = threadIdx.x;
    const int wid = tid >> 5;
    const int lane = tid & 31;
    const int g = lane >> 2;
    const int tig = lane & 3;
    const int quad = lane >> 3;
    const int rowin = lane & 7;
    const int warp_m = wid & 1;
    const int warp_n = wid >> 1;
    const int m0 = warp_m * 32;
    const int n0 = warp_n * 32;

    const int is64 = g_idx64;
    const long long e0 = (long long)blockIdx.x * TILE_E;

    // ---- prologue: stage rbf chunk into slot 0 ----
    stage_chunk(Abase + A_BYTES, g_W1rbfT, 0, 32, 32, tid);

    // ---- build A meta + rbf: 8 threads per edge, no s gather ----
    {
        const int m = tid >> 3;
        const int c = tid & 7;
        const bool valid = (e0 + m) < (long long)E;
        uint32_t* Arow = A32 + m * APAIRS;
        if (valid) {
            long long srcI = load_idx(eidx, e0 + m, is64);
            long long dstI = load_idx(eidx, (long long)E + e0 + m, is64);
            if (c == 0) {
                float rx = pos[dstI * 3 + 0] - pos[srcI * 3 + 0];
                float ry = pos[dstI * 3 + 1] - pos[srcI * 3 + 1];
                float rz = pos[dstI * 3 + 2] - pos[srcI * 3 + 2];
                float d2 = rx * rx + ry * ry + rz * rz;
                float dist = sqrtf(d2);
                float inv = (d2 > 0.f) ? (1.0f / dist) : 0.0f;
                Arow[M_SRC]  = (uint32_t)(int)srcI;
                Arow[M_DST]  = (uint32_t)(int)dstI;
                Arow[M_DIRX] = __float_as_uint(rx * inv);
                Arow[M_DIRY] = __float_as_uint(ry * inv);
                Arow[M_DIRZ] = __float_as_uint(rz * inv);
            } else if (c == 7) {
                float rx = pos[dstI * 3 + 0] - pos[srcI * 3 + 0];
                float ry = pos[dstI * 3 + 1] - pos[srcI * 3 + 1];
                float rz = pos[dstI * 3 + 2] - pos[srcI * 3 + 2];
                float dist = sqrtf(rx * rx + ry * ry + rz * rz);
#pragma unroll
                for (int j = 0; j < 10; ++j) {   // rbf pairs 0..9
                    float t0 = (dist - __ldg(centers + 2 * j)) /
                               (__ldg(widths + 2 * j) + 1e-8f);
                    float t1 = (dist - __ldg(centers + 2 * j + 1)) /
                               (__ldg(widths + 2 * j + 1) + 1e-8f);
                    Arow[j] = packbf(__expf(-t0 * t0), __expf(-t1 * t1));
                }
#pragma unroll
                for (int j = 10; j < 16; ++j) Arow[j] = 0;   // pad K to 32
            }
        } else {
            if (c == 0) {
                Arow[M_SRC] = (uint32_t)(-1);
                Arow[M_DST] = (uint32_t)(-1);
                Arow[M_DIRX] = 0; Arow[M_DIRY] = 0; Arow[M_DIRZ] = 0;
            } else if (c == 7) {
#pragma unroll
                for (int j = 0; j < 16; ++j) Arow[j] = 0;
            }
        }
    }
    __syncthreads();

    float acc[2][4][4];
    int gc = 0;

#pragma unroll 1
    for (int L = 0; L < 3; ++L) {
        const int nch = (L == 0) ? 1 : 4;

#pragma unroll
        for (int mb = 0; mb < 2; ++mb)
#pragma unroll
            for (int t = 0; t < 4; ++t)
#pragma unroll
                for (int i = 0; i < 4; ++i) acc[mb][t][i] = 0.f;

#pragma unroll 1
        for (int c = 0; c < nch; ++c) {
            const int gcl = gc;
            const __nv_bfloat16* w; int c0, Kl, kw;
            chunk_src(gcl, w, c0, Kl, kw);

            asm volatile("cp.async.wait_group 0;" ::: "memory");
            __syncthreads();
            if (gcl + 1 < NCHUNK_TOT) {
                const __nv_bfloat16* nw; int nc0, nKl, nkw;
                chunk_src(gcl + 1, nw, nc0, nKl, nkw);
                stage_chunk(Abase + A_BYTES + ((gcl + 1) & 1) * B_BYTES, nw, nc0, nKl, nkw,
                            tid);
            }

            const uint32_t Bc = Abase + A_BYTES + (gcl & 1) * B_BYTES;
            const int nks = kw >> 4;
#pragma unroll 1
            for (int ks = 0; ks < nks; ++ks) {
                const int KPa = (c0 >> 1) + ks * 8;
                const int KBb = ks * 32;
                uint32_t afr[2][4];
#pragma unroll
                for (int mb = 0; mb < 2; ++mb) {
                    int row = m0 + mb * 16 + (quad & 1) * 8 + rowin;
                    int kp = KPa + (quad >> 1) * 4;
                    ldm_x4(afr[mb], Abase + (uint32_t)row * AROW_BYTES + (uint32_t)kp * 4u);
                }
#pragma unroll
                for (int tp = 0; tp < 2; ++tp) {
                    uint32_t bfr[4];
                    int n = n0 + tp * 16 + (quad >> 1) * 8 + rowin;
                    ldm_x4(bfr, Bc + (uint32_t)n * BROW_BYTES + KBb + (quad & 1) * 16);
#pragma unroll
                    for (int mb = 0; mb < 2; ++mb) {
                        mma16816(acc[mb][2 * tp], afr[mb][0], afr[mb][1], afr[mb][2],
                                 afr[mb][3], bfr[0], bfr[1]);
                        mma16816(acc[mb][2 * tp + 1], afr[mb][0], afr[mb][1], afr[mb][2],
                                 afr[mb][3], bfr[2], bfr[3]);
                    }
                }
            }
            gc++;
        }
        __syncthreads();   // layer compute done before A overwrite / scatter

        if (L == 0) {
            // ---- h1 = silu(rbf_acc + pre_a[src] + pre_b[dst] + b1) ----
#pragma unroll
            for (int mb = 0; mb < 2; ++mb) {
                const int r0 = m0 + mb * 16 + g, r1 = r0 + 8;
                const int s0 = (int)A32[r0 * APAIRS + M_SRC];
                const int d0 = (int)A32[r0 * APAIRS + M_DST];
                const int s1 = (int)A32[r1 * APAIRS + M_SRC];
                const int d1 = (int)A32[r1 * APAIRS + M_DST];
#pragma unroll
                for (int t = 0; t < 4; ++t) {
                    const int col = n0 + t * 8 + tig * 2;
                    float bb0 = __ldg(b1 + col), bb1 = __ldg(b1 + col + 1);
                    float pa0l = 0.f, pa0h = 0.f, pb0l = 0.f, pb0h = 0.f;
                    float pa1l = 0.f, pa1h = 0.f, pb1l = 0.f, pb1h = 0.f;
                    if (s0 >= 0) {
                        uint32_t ua = *(const uint32_t*)((const char*)g_pre +
                                      ((size_t)s0 * 512 + col) * 2);
                        uint32_t ub = *(const uint32_t*)((const char*)g_pre +
                                      ((size_t)d0 * 512 + 256 + col) * 2);
                        unpk(ua, pa0l, pa0h);
                        unpk(ub, pb0l, pb0h);
                    }
                    if (s1 >= 0) {
                        uint32_t ua = *(const uint32_t*)((const char*)g_pre +
                                      ((size_t)s1 * 512 + col) * 2);
                        uint32_t ub = *(const uint32_t*)((const char*)g_pre +
                                      ((size_t)d1 * 512 + 256 + col) * 2);
                        unpk(ua, pa1l, pa1h);
                        unpk(ub, pb1l, pb1h);
                    }
                    const int pr = col >> 1;
                    A32[r0 * APAIRS + pr] =
                        packbf(silu(acc[mb][t][0] + pa0l + pb0l + bb0),
                               silu(acc[mb][t][1] + pa0h + pb0h + bb1));
                    A32[r1 * APAIRS + pr] =
                        packbf(silu(acc[mb][t][2] + pa1l + pb1l + bb0),
                               silu(acc[mb][t][3] + pa1h + pb1h + bb1));
                }
            }
        } else if (L == 1) {
            // ---- h2 = silu(acc + b2) ----
#pragma unroll
            for (int mb = 0; mb < 2; ++mb) {
                const int r0 = m0 + mb * 16 + g;
#pragma unroll
                for (int t = 0; t < 4; ++t) {
                    const int col = n0 + t * 8 + tig * 2;
                    float bb0 = __ldg(b2 + col), bb1 = __ldg(b2 + col + 1);
                    const int pr = col >> 1;
                    A32[r0 * APAIRS + pr] =
                        packbf(silu(acc[mb][t][0] + bb0), silu(acc[mb][t][1] + bb1));
                    A32[(r0 + 8) * APAIRS + pr] =
                        packbf(silu(acc[mb][t][2] + bb0), silu(acc[mb][t][3] + bb1));
                }
            }
        } else {
            // ---- scatter: warp_n 0-3 -> ds; warp_n 4-7 -> dv ----
#pragma unroll
            for (int mb = 0; mb < 2; ++mb) {
                const int r0 = m0 + mb * 16 + g, r1 = r0 + 8;
                const int d0 = (int)A32[r0 * APAIRS + M_DST];
                const int d1 = (int)A32[r1 * APAIRS + M_DST];
                if (n0 < 128) {
#pragma unroll
                    for (int t = 0; t < 4; ++t) {
                        const int col = n0 + t * 8 + tig * 2;
                        float bb0 = __ldg(bs + col), bb1 = __ldg(bs + col + 1);
                        if (d0 >= 0)
                            red2(out_s + (long long)d0 * FDIM + col, acc[mb][t][0] + bb0,
                                 acc[mb][t][1] + bb1);
                        if (d1 >= 0)
                            red2(out_s + (long long)d1 * FDIM + col, acc[mb][t][2] + bb0,
                                 acc[mb][t][3] + bb1);
                    }
                } else {
                    float dx0 = __uint_as_float(A32[r0 * APAIRS + M_DIRX]);
                    float dy0 = __uint_as_float(A32[r0 * APAIRS + M_DIRY]);
                    float dz0 = __uint_as_float(A32[r0 * APAIRS + M_DIRZ]);
                    float dx1 = __uint_as_float(A32[r1 * APAIRS + M_DIRX]);
                    float dy1 = __uint_as_float(A32[r1 * APAIRS + M_DIRY]);
                    float dz1 = __uint_as_float(A32[r1 * APAIRS + M_DIRZ]);
#pragma unroll
                    for (int t = 0; t < 4; ++t) {
                        const int col = n0 - 128 + t * 8 + tig * 2;
                        float bb0 = __ldg(bv + col), bb1 = __ldg(bv + col + 1);
                        if (d0 >= 0) {
                            float v0 = acc[mb][t][0] + bb0, v1 = acc[mb][t][1] + bb1;
                            float* vb = out_v + (long long)d0 * 3 * FDIM + col;
                            red2(vb, dx0 * v0, dx0 * v1);
                            red2(vb + FDIM, dy0 * v0, dy0 * v1);
                            red2(vb + 2 * FDIM, dz0 * v0, dz0 * v1);
                        }
                        if (d1 >= 0) {
                            float v0 = acc[mb][t][2] + bb0, v1 = acc[mb][t][3] + bb1;
                            float* vb = out_v + (long long)d1 * 3 * FDIM + col;
                            red2(vb, dx1 * v0, dx1 * v1);
                            red2(vb + FDIM, dy1 * v0, dy1 * v1);
                            red2(vb + 2 * FDIM, dz1 * v0, dz1 * v1);
                        }
                    }
                }
            }
        }
    }
}

// ---------------- launcher ----------------
extern "C" void kernel_launch(void* const* d_in, const int* in_sizes, int n_in,
                              void* d_out, int out_size) {
    const float* s       = (const float*)d_in[0];
    const float* v       = (const float*)d_in[1];
    const float* pos     = (const float*)d_in[2];
    const void*  eidx    = d_in[3];
    const float* W1      = (const float*)d_in[4];
    const float* b1      = (const float*)d_in[5];
    const float* W2      = (const float*)d_in[6];
    const float* b2      = (const float*)d_in[7];
    const float* Ws      = (const float*)d_in[8];
    const float* bs      = (const float*)d_in[9];
    const float* Wv      = (const float*)d_in[10];
    const float* bv      = (const float*)d_in[11];
    const float* centers = (const float*)d_in[12];
    const float* widths  = (const float*)d_in[13];

    int N = in_sizes[0] / FDIM;
    int E = in_sizes[3] / 2;

    float* out_s = (float*)d_out;
    float* out_v = out_s + (long long)N * FDIM;

    detect_idx_kernel<<<1, 256>>>((const int*)eidx);

    int ns4 = N * FDIM / 4;
    int nv4 = N * 3 * FDIM / 4;
    init_out_kernel<<<1024, 256>>>((const float4*)s, (const float4*)v, (float4*)d_out, ns4, nv4);

    prep_weights<<<512, 256>>>(W1, W2, Ws, Wv, s, N * FDIM);

    cudaFuncSetAttribute(prep_pre_kernel, cudaFuncAttributeMaxDynamicSharedMemorySize,
                         P_SMEM);
    prep_pre_kernel<<<(N + 63) / 64, NTHREADS, P_SMEM>>>(N);

    cudaFuncSetAttribute(painn_mma_kernel, cudaFuncAttributeMaxDynamicSharedMemorySize,
                         SMEM_TOTAL);
    int grid = (E + TILE_E - 1) / TILE_E;
    painn_mma_kernel<<<grid, NTHREADS, SMEM_TOTAL>>>(pos, eidx, b1, b2, bs, bv, centers,
                                                     widths, out_s, out_v, E);
}